// round 16
// baseline (speedup 1.0000x reference)
#include <cuda_runtime.h>

// PCLSTM: B=20, C=395, H=10, T=8192.
// Fused: blocks [0,20) = recurrence (1 warp, 1 batch each); blocks [20,660) =
// gate pre-activation GEMM tiles ((chunk-of-256-t) x batch), publishing per-chunk
// ready flags that the recurrence warps chase.
// Recurrence step (lane j = lane%10, all gates lane-local):
//   h broadcast: 10 shfl, packed k-paired hp[q]=(h2q,h2q+1) (register-coalesced),
//   4 gate accumulators with k-paired weights (5 FFMA2 each), horizontal FADD,
//   tanh.approx activations. sigmoid via 0.5+0.5*tanh(0.5z), 0.5 pre-folded.
// c0 = b_init (W_init mathematically unused).

#define Bk 20
#define Ck 395
#define Hk 10
#define Tk 8192
#define GIN 800
#define CHUNK 32
#define NCHUNKS 32     // Tk / 256
#define TCH 256

typedef unsigned long long ull;

// pre buffer: [b][t][h] float4 (x=.5*zf, y=.5*zi, z=zu, w=.5*zo) + pad for prefetch overrun
__device__ __align__(16) float4 g_pre[(size_t)Bk * Tk * 10 + 512];
__device__ int g_ready[NCHUNKS];
__device__ __align__(16) float g_dump[64];   // sink for non-owner lane stores

__device__ __forceinline__ ull pack2(float a, float b) {
    ull r; asm("mov.b64 %0, {%1,%2};" : "=l"(r) : "f"(a), "f"(b)); return r;
}
__device__ __forceinline__ void unpack2(ull v, float& a, float& b) {
    asm("mov.b64 {%0,%1}, %2;" : "=f"(a), "=f"(b) : "l"(v));
}
__device__ __forceinline__ void ffma2(ull& d, ull a, ull b) {
    asm("fma.rn.f32x2 %0, %1, %2, %0;" : "+l"(d) : "l"(a), "l"(b));
}
__device__ __forceinline__ float tanhf_a(float x) {
    float r; asm("tanh.approx.f32 %0, %1;" : "=f"(r) : "f"(x)); return r;
}
__device__ __forceinline__ int ld_acq(const int* p) {
    int v; asm volatile("ld.acquire.gpu.b32 %0, [%1];" : "=r"(v) : "l"(p) : "memory");
    return v;
}

__global__ void zero_flags() {
    if (threadIdx.x < NCHUNKS) g_ready[threadIdx.x] = 0;
}

// ---------------------------------------------------------------------------
// One LSTM step, fully lane-local except the h broadcast.
// pf pre-scaled: x=.5*zf, y=.5*zi, z=zu, w=.5*zo.
// wf/wi/wu/wo: k-paired Wh rows (w[q] = (W[j][2q], W[j][2q+1])), 0.5-folded for f,i,o.
// ---------------------------------------------------------------------------
__device__ __forceinline__ float step_all(
    float4 pf, float& hval, float& cval,
    const ull* wf, const ull* wi, const ull* wu, const ull* wo)
{
    float s0 = __shfl_sync(0xffffffffu, hval, 0);
    float s1 = __shfl_sync(0xffffffffu, hval, 1);
    float s2 = __shfl_sync(0xffffffffu, hval, 2);
    float s3 = __shfl_sync(0xffffffffu, hval, 3);
    float s4 = __shfl_sync(0xffffffffu, hval, 4);
    float s5 = __shfl_sync(0xffffffffu, hval, 5);
    float s6 = __shfl_sync(0xffffffffu, hval, 6);
    float s7 = __shfl_sync(0xffffffffu, hval, 7);
    float s8 = __shfl_sync(0xffffffffu, hval, 8);
    float s9 = __shfl_sync(0xffffffffu, hval, 9);
    ull hp0 = pack2(s0, s1);   // coalescible: distinct producers into a reg pair
    ull hp1 = pack2(s2, s3);
    ull hp2 = pack2(s4, s5);
    ull hp3 = pack2(s6, s7);
    ull hp4 = pack2(s8, s9);

    ull af = pack2(pf.x, 0.0f);   // built off-chain (pf available early)
    ull ai = pack2(pf.y, 0.0f);
    ull au = pack2(pf.z, 0.0f);
    ull ao = pack2(pf.w, 0.0f);

    ffma2(af, hp0, wf[0]); ffma2(ai, hp0, wi[0]); ffma2(au, hp0, wu[0]); ffma2(ao, hp0, wo[0]);
    ffma2(af, hp1, wf[1]); ffma2(ai, hp1, wi[1]); ffma2(au, hp1, wu[1]); ffma2(ao, hp1, wo[1]);
    ffma2(af, hp2, wf[2]); ffma2(ai, hp2, wi[2]); ffma2(au, hp2, wu[2]); ffma2(ao, hp2, wo[2]);
    ffma2(af, hp3, wf[3]); ffma2(ai, hp3, wi[3]); ffma2(au, hp3, wu[3]); ffma2(ao, hp3, wo[3]);
    ffma2(af, hp4, wf[4]); ffma2(ai, hp4, wi[4]); ffma2(au, hp4, wu[4]); ffma2(ao, hp4, wo[4]);

    float flo, fhi, ilo, ihi, ulo, uhi, olo, ohi;
    unpack2(af, flo, fhi);   // register aliasing, ~free
    unpack2(ai, ilo, ihi);
    unpack2(au, ulo, uhi);
    unpack2(ao, olo, ohi);
    float zf = flo + fhi;
    float zi = ilo + ihi;
    float zu = ulo + uhi;
    float zo = olo + ohi;

    float tf = tanhf_a(zf);              // c-critical first
    float ti = tanhf_a(zi);
    float tg = tanhf_a(zu);
    float fv = fmaf(0.5f, tf, 0.5f);
    float iv = fmaf(0.5f, ti, 0.5f);
    float ig = iv * tg;
    cval = fmaf(cval, fv, ig);
    float to = tanhf_a(zo);
    float ov = fmaf(0.5f, to, 0.5f);
    float tc = tanhf_a(cval);
    hval = ov * tc;
    return hval;
}

__device__ __forceinline__ void spin_chunk(int k) {
    #pragma unroll 1
    while (ld_acq(&g_ready[k]) < Bk) { }
}

#define LOAD8(dst, base, tt)                                             \
    do {                                                                 \
        const float4* _p = (base) + (size_t)(tt) * 10;                   \
        dst##0 = _p[0];  dst##1 = _p[10]; dst##2 = _p[20]; dst##3 = _p[30]; \
        dst##4 = _p[40]; dst##5 = _p[50]; dst##6 = _p[60]; dst##7 = _p[70]; \
    } while (0)

// ---------------------------------------------------------------------------
__global__ __launch_bounds__(128) void pclstm_fused(
    const float* __restrict__ x, const float* __restrict__ y,
    const float* __restrict__ Wf, const float* __restrict__ bf,
    const float* __restrict__ Wi, const float* __restrict__ bi,
    const float* __restrict__ Wu, const float* __restrict__ bu,
    const float* __restrict__ Wo, const float* __restrict__ bo,
    const float* __restrict__ b_init, float* __restrict__ out)
{
    __shared__ __align__(16) ull sWx[CHUNK * 40];
    __shared__ __align__(16) ull sWy[CHUNK * 40];

    const int tid = threadIdx.x;
    const int bx  = blockIdx.x;

    if (bx < Bk) {
        // ================= recurrence role (1 warp per batch) =================
        if (tid >= 32) return;
        const int lane = tid;
        const int j = lane % 10;
        const bool owner = (lane < 10);

        ull wf2[5], wi2[5], wu2[5], wo2[5];
        #pragma unroll
        for (int q = 0; q < 5; ++q) {
            wf2[q] = pack2(0.5f * Wf[j * GIN + Ck + 2 * q], 0.5f * Wf[j * GIN + Ck + 2 * q + 1]);
            wi2[q] = pack2(0.5f * Wi[j * GIN + Ck + 2 * q], 0.5f * Wi[j * GIN + Ck + 2 * q + 1]);
            wu2[q] = pack2(Wu[j * GIN + Ck + 2 * q],        Wu[j * GIN + Ck + 2 * q + 1]);
            wo2[q] = pack2(0.5f * Wo[j * GIN + Ck + 2 * q], 0.5f * Wo[j * GIN + Ck + 2 * q + 1]);
        }

        float hval = 0.0f;
        float cval = b_init[j];

        const float4* pp = g_pre + (size_t)bx * Tk * 10 + j;
        float* op = out + ((size_t)bx * Hk + j) * Tk;

        spin_chunk(0);
        float4 A0, A1, A2, A3, A4, A5, A6, A7;
        float4 B0, B1, B2, B3, B4, B5, B6, B7;
        LOAD8(A, pp, 0);
        LOAD8(B, pp, 8);

        #pragma unroll 1
        for (int kc = 0; kc < NCHUNKS; ++kc) {
            spin_chunk(kc < NCHUNKS - 1 ? kc + 1 : NCHUNKS - 1);
            const int tend = kc * TCH + TCH;
            #pragma unroll 1
            for (int t0 = kc * TCH; t0 < tend; t0 += 16) {
                // ---- half 1: steps t0..t0+7 from A; refill A <- t0+16 ----
                float h0 = step_all(A0, hval, cval, wf2, wi2, wu2, wo2);
                float h1 = step_all(A1, hval, cval, wf2, wi2, wu2, wo2);
                float h2 = step_all(A2, hval, cval, wf2, wi2, wu2, wo2);
                float h3 = step_all(A3, hval, cval, wf2, wi2, wu2, wo2);
                float h4 = step_all(A4, hval, cval, wf2, wi2, wu2, wo2);
                float h5 = step_all(A5, hval, cval, wf2, wi2, wu2, wo2);
                float h6 = step_all(A6, hval, cval, wf2, wi2, wu2, wo2);
                float h7 = step_all(A7, hval, cval, wf2, wi2, wu2, wo2);
                {
                    float4* s0 = owner ? (float4*)(op + t0)     : (float4*)g_dump;
                    float4* s1 = owner ? (float4*)(op + t0 + 4) : (float4*)(g_dump + 4);
                    *s0 = make_float4(h0, h1, h2, h3);
                    *s1 = make_float4(h4, h5, h6, h7);
                }
                LOAD8(A, pp, t0 + 16);   // pad covers end-of-time overrun

                // ---- half 2: steps t0+8..t0+15 from B; refill B <- t0+24 ----
                h0 = step_all(B0, hval, cval, wf2, wi2, wu2, wo2);
                h1 = step_all(B1, hval, cval, wf2, wi2, wu2, wo2);
                h2 = step_all(B2, hval, cval, wf2, wi2, wu2, wo2);
                h3 = step_all(B3, hval, cval, wf2, wi2, wu2, wo2);
                h4 = step_all(B4, hval, cval, wf2, wi2, wu2, wo2);
                h5 = step_all(B5, hval, cval, wf2, wi2, wu2, wo2);
                h6 = step_all(B6, hval, cval, wf2, wi2, wu2, wo2);
                h7 = step_all(B7, hval, cval, wf2, wi2, wu2, wo2);
                {
                    float4* s0 = owner ? (float4*)(op + t0 + 8)  : (float4*)g_dump;
                    float4* s1 = owner ? (float4*)(op + t0 + 12) : (float4*)(g_dump + 4);
                    *s0 = make_float4(h0, h1, h2, h3);
                    *s1 = make_float4(h4, h5, h6, h7);
                }
                LOAD8(B, pp, t0 + 24);   // pad covers end-of-time overrun
            }
        }
        if (owner) out[(size_t)Bk * Hk * Tk + bx * Hk + j] = cval;
        return;
    }

    // ================= GEMM role: one (chunk, batch) tile =================
    const int g     = bx - Bk;
    const int b     = g % Bk;        // batch varies fastest -> chunk-major completion
    const int chunk = g / Bk;
    const int t     = chunk * TCH + tid * 2;

    ull acc[40];
    #pragma unroll
    for (int h = 0; h < Hk; ++h) {
        acc[h]      = pack2(bf[h], bf[h]);
        acc[10 + h] = pack2(bi[h], bi[h]);
        acc[20 + h] = pack2(bu[h], bu[h]);
        acc[30 + h] = pack2(bo[h], bo[h]);
    }

    for (int c0 = 0; c0 < Ck; c0 += CHUNK) {
        const int clen = min(CHUNK, Ck - c0);
        __syncthreads();
        for (int idx = tid; idx < clen * 40; idx += 128) {
            int cl = idx / 40;
            int gh = idx - cl * 40;
            int gg = gh / 10;
            int h  = gh - gg * 10;
            const float* Wgp = (gg == 0) ? Wf : ((gg == 1) ? Wi : ((gg == 2) ? Wu : Wo));
            int col = c0 + cl;
            float wx  = Wgp[h * GIN + col];
            float wyv = Wgp[h * GIN + (Ck + Hk) + col];
            sWx[cl * 40 + gh] = pack2(wx, wx);
            sWy[cl * 40 + gh] = pack2(wyv, wyv);
        }
        __syncthreads();

        const float* xp = x + ((size_t)(b * Ck + c0)) * Tk + t;
        const float* yp = y + ((size_t)(b * Ck + c0)) * Tk + t;
        for (int cl = 0; cl < clen; ++cl) {
            float2 xv = *(const float2*)xp;
            float ya = (t > 0) ? yp[-1] : 0.0f;   // y_prev[t]   = y[t-1]
            float yb = yp[0];                     // y_prev[t+1] = y[t]
            ull X2 = pack2(xv.x, xv.y);
            ull Y2 = pack2(ya, yb);
            const ulonglong2* wx2 = (const ulonglong2*)&sWx[cl * 40];
            const ulonglong2* wy2 = (const ulonglong2*)&sWy[cl * 40];
            #pragma unroll
            for (int q = 0; q < 20; ++q) {
                ulonglong2 wv = wx2[q];
                ffma2(acc[2 * q],     X2, wv.x);
                ffma2(acc[2 * q + 1], X2, wv.y);
            }
            #pragma unroll
            for (int q = 0; q < 20; ++q) {
                ulonglong2 wv = wy2[q];
                ffma2(acc[2 * q],     Y2, wv.x);
                ffma2(acc[2 * q + 1], Y2, wv.y);
            }
            xp += Tk; yp += Tk;
        }
    }

    // Epilogue: fold sigmoid 0.5 scaling (f,i,o); u unscaled. Store [t][h][gate] float4.
    float4* outp = g_pre + ((size_t)b * Tk + t) * 10;
    #pragma unroll
    for (int h = 0; h < Hk; ++h) {
        float f0, f1, i0, i1, u0, u1, o0, o1;
        unpack2(acc[h],      f0, f1);
        unpack2(acc[10 + h], i0, i1);
        unpack2(acc[20 + h], u0, u1);
        unpack2(acc[30 + h], o0, o1);
        outp[h]      = make_float4(0.5f * f0, 0.5f * i0, u0, 0.5f * o0);
        outp[10 + h] = make_float4(0.5f * f1, 0.5f * i1, u1, 0.5f * o1);
    }

    __threadfence();
    __syncthreads();
    if (tid == 0) atomicAdd(&g_ready[chunk], 1);
}

// ---------------------------------------------------------------------------
extern "C" void kernel_launch(void* const* d_in, const int* in_sizes, int n_in,
                              void* d_out, int out_size)
{
    const float* x      = (const float*)d_in[0];
    const float* y      = (const float*)d_in[1];
    const float* Wf     = (const float*)d_in[2];
    const float* bf     = (const float*)d_in[3];
    const float* Wi     = (const float*)d_in[4];
    const float* bi     = (const float*)d_in[5];
    const float* Wu     = (const float*)d_in[6];
    const float* bu     = (const float*)d_in[7];
    const float* Wo     = (const float*)d_in[8];
    const float* bo     = (const float*)d_in[9];
    // d_in[10] = W_init: unused (c0 = 0 @ W_init.T + b_init == b_init)
    const float* b_init = (const float*)d_in[11];
    float* out = (float*)d_out;
    (void)in_sizes; (void)n_in; (void)out_size;

    zero_flags<<<1, 32>>>();
    pclstm_fused<<<Bk + NCHUNKS * Bk, 128>>>(x, y, Wf, bf, Wi, bi, Wu, bu, Wo, bo,
                                             b_init, out);
}